// round 17
// baseline (speedup 1.0000x reference)
#include <cuda_runtime.h>
#include <cstdint>
#include <cstddef>

// CrossLevelAttention via fp16 mma.sync.m16n8k16 flash attention.
// CTA: 128 threads / 4 warps, 64 q rows (16/warp), BN=64 key tiles.
// K/V converted fp32->fp16 on the fly (LDG-staged in regs, cvt+STS at tile
// boundary; single-buffered 16KB smem). K/V stored in ldmatrix-native 128B
// blocks: block(s=key/8, j=dh/8) holds 8 keys x 8 dh -> every ldsm4 (and
// ldsm4.trans for V) is conflict-free. P C-layout packs directly into the
// fp16 A-fragment (cvt.rn.f16x2) -- no shuffles, no V permutation.
// PV pipelined one kstep (=2 slices) behind S. exp via ex2 (log2e in Q).
// Per-level output accumulated into gmem (RMW).

#define NHEAD 16
#define DH 64
#define CDIM (NHEAD * DH)
#define BM 64
#define BN 64
#define SCALE_L2E 0.18033688011112042592f   // 0.125 * log2(e)
#define KTILE_B 8192                         // 64x64 fp16

__device__ __forceinline__ float ex2f(float x) {
    float y;
    asm("ex2.approx.f32 %0, %1;" : "=f"(y) : "f"(x));
    return y;
}

// pack two f32 into f16x2: lo in low half. (PTX: cvt d, a, b -> hi=a, lo=b)
__device__ __forceinline__ uint32_t pack_h2(float lo, float hi) {
    uint32_t d;
    asm("cvt.rn.f16x2.f32 %0, %1, %2;" : "=r"(d) : "f"(hi), "f"(lo));
    return d;
}

__device__ __forceinline__ void mma_f16(
    float& c0, float& c1, float& c2, float& c3,
    uint32_t a0, uint32_t a1, uint32_t a2, uint32_t a3,
    uint32_t b0, uint32_t b1)
{
    asm volatile(
        "mma.sync.aligned.m16n8k16.row.col.f32.f16.f16.f32 "
        "{%0,%1,%2,%3}, {%4,%5,%6,%7}, {%8,%9}, {%0,%1,%2,%3};"
        : "+f"(c0), "+f"(c1), "+f"(c2), "+f"(c3)
        : "r"(a0), "r"(a1), "r"(a2), "r"(a3), "r"(b0), "r"(b1));
}

__device__ __forceinline__ void ldsm4(
    uint32_t& r0, uint32_t& r1, uint32_t& r2, uint32_t& r3, uint32_t saddr)
{
    asm volatile("ldmatrix.sync.aligned.m8n8.x4.shared.b16 {%0,%1,%2,%3}, [%4];"
                 : "=r"(r0), "=r"(r1), "=r"(r2), "=r"(r3) : "r"(saddr));
}

__device__ __forceinline__ void ldsm4t(
    uint32_t& r0, uint32_t& r1, uint32_t& r2, uint32_t& r3, uint32_t saddr)
{
    asm volatile("ldmatrix.sync.aligned.m8n8.x4.trans.shared.b16 {%0,%1,%2,%3}, [%4];"
                 : "=r"(r0), "=r"(r1), "=r"(r2), "=r"(r3) : "r"(saddr));
}

// Stage one 64x64 fp32 K and V tile into 16 float4 registers.
__device__ __forceinline__ void ldg_tile(
    const float* __restrict__ kb, const float* __restrict__ vb,
    int kt, float4 (&kst)[8], float4 (&vst)[8], int tid)
{
    #pragma unroll
    for (int it = 0; it < 4; it++) {
        int rid = it * 128 + tid;          // (key n, dh-chunk j): 512 rows
        int n = rid >> 3;
        int j = rid & 7;
        const float* ks = kb + (size_t)(kt + n) * CDIM + j * 8;
        const float* vs = vb + (size_t)(kt + n) * CDIM + j * 8;
        kst[it * 2]     = *reinterpret_cast<const float4*>(ks);
        kst[it * 2 + 1] = *reinterpret_cast<const float4*>(ks + 4);
        vst[it * 2]     = *reinterpret_cast<const float4*>(vs);
        vst[it * 2 + 1] = *reinterpret_cast<const float4*>(vs + 4);
    }
}

// Convert staged fp32 to fp16 and store into blocked smem layout:
// block(s=key/8, j=dh/8) at (s*8+j)*128 bytes; row r=key&7 -> +r*16.
__device__ __forceinline__ void sts_tile(
    const float4 (&kst)[8], const float4 (&vst)[8],
    char* sK, char* sV, int tid)
{
    #pragma unroll
    for (int it = 0; it < 4; it++) {
        int rid = it * 128 + tid;
        int n = rid >> 3;
        int j = rid & 7;
        int off = ((n >> 3) * 8 + j) * 128 + (n & 7) * 16;
        float4 a = kst[it * 2], b = kst[it * 2 + 1];
        uint4 hk = make_uint4(pack_h2(a.x, a.y), pack_h2(a.z, a.w),
                              pack_h2(b.x, b.y), pack_h2(b.z, b.w));
        *reinterpret_cast<uint4*>(sK + off) = hk;
        float4 c = vst[it * 2], d = vst[it * 2 + 1];
        uint4 hv = make_uint4(pack_h2(c.x, c.y), pack_h2(c.z, c.w),
                              pack_h2(d.x, d.y), pack_h2(d.z, d.w));
        *reinterpret_cast<uint4*>(sV + off) = hv;
    }
}

// One attention level; writes (FIRST) / RMW-adds weighted result into out.
template <bool CAUSAL, bool FIRST>
__device__ __forceinline__ void attend_level(
    const float* __restrict__ kbase, const float* __restrict__ vbase,
    int n_keys, int q0, int g, int c, int tid, int r0q,
    const uint32_t (&qf)[4][4], float lw,
    char* sK, char* sV, uint32_t kLane, uint32_t vLane,
    float* __restrict__ outp)
{
    float o[32];
    #pragma unroll
    for (int i = 0; i < 32; i++) o[i] = 0.f;
    float rs0 = 0.f, rs1 = 0.f;
    const int r1q = r0q + 8;
    const int ntile = n_keys / BN;

    const uint32_t kBaseS = (uint32_t)__cvta_generic_to_shared(sK) + kLane;
    const uint32_t vBaseS = (uint32_t)__cvta_generic_to_shared(sV) + vLane;

    float4 kst[8], vst[8];
    ldg_tile(kbase, vbase, 0, kst, vst, tid);

    for (int t = 0; t < ntile; t++) {
        __syncthreads();                 // previous tile compute done (all warps)
        sts_tile(kst, vst, sK, sV, tid); // convert + store tile t
        __syncthreads();                 // tile t visible
        if (t + 1 < ntile)
            ldg_tile(kbase, vbase, (t + 1) * BN, kst, vst, tid);

        const int kt = t * BN;
        const bool dom = CAUSAL && (kt + BN > q0);
        uint32_t pa0 = 0, pa1 = 0, pa2 = 0, pa3 = 0;  // P A-frag of kstep sp-1

        #pragma unroll
        for (int sp = 0; sp < 4; sp++) {   // kstep sp = slices 2sp, 2sp+1
            // ---- K frags: slice 2sp (ka) and 2sp+1 (kc) ----
            uint32_t ka[8], kc[8];
            uint32_t sa = kBaseS + (uint32_t)(sp * 2048);
            ldsm4(ka[0], ka[1], ka[2], ka[3], sa);
            ldsm4(ka[4], ka[5], ka[6], ka[7], sa + 512);
            ldsm4(kc[0], kc[1], kc[2], kc[3], sa + 1024);
            ldsm4(kc[4], kc[5], kc[6], kc[7], sa + 1536);

            // ---- S slices: two depth-2 chains each ----
            float aA0 = 0.f, aA1 = 0.f, aA2 = 0.f, aA3 = 0.f;
            float aB0 = 0.f, aB1 = 0.f, aB2 = 0.f, aB3 = 0.f;
            mma_f16(aA0, aA1, aA2, aA3, qf[0][0], qf[0][1], qf[0][2], qf[0][3],
                    ka[0], ka[1]);
            mma_f16(aB0, aB1, aB2, aB3, qf[2][0], qf[2][1], qf[2][2], qf[2][3],
                    ka[4], ka[5]);
            mma_f16(aA0, aA1, aA2, aA3, qf[1][0], qf[1][1], qf[1][2], qf[1][3],
                    ka[2], ka[3]);
            mma_f16(aB0, aB1, aB2, aB3, qf[3][0], qf[3][1], qf[3][2], qf[3][3],
                    ka[6], ka[7]);

            float bA0 = 0.f, bA1 = 0.f, bA2 = 0.f, bA3 = 0.f;
            float bB0 = 0.f, bB1 = 0.f, bB2 = 0.f, bB3 = 0.f;
            mma_f16(bA0, bA1, bA2, bA3, qf[0][0], qf[0][1], qf[0][2], qf[0][3],
                    kc[0], kc[1]);
            mma_f16(bB0, bB1, bB2, bB3, qf[2][0], qf[2][1], qf[2][2], qf[2][3],
                    kc[4], kc[5]);
            mma_f16(bA0, bA1, bA2, bA3, qf[1][0], qf[1][1], qf[1][2], qf[1][3],
                    kc[2], kc[3]);
            mma_f16(bB0, bB1, bB2, bB3, qf[3][0], qf[3][1], qf[3][2], qf[3][3],
                    kc[6], kc[7]);

            // ---- PV for kstep sp-1 (overlaps S chains above) ----
            if (sp > 0) {
                uint32_t vbase_t = vBaseS + (uint32_t)((sp - 1) * 2048);
                #pragma unroll
                for (int jj = 0; jj < 8; jj += 2) {
                    uint32_t v0, v1, v2, v3;
                    ldsm4t(v0, v1, v2, v3, vbase_t + (uint32_t)(jj * 128));
                    mma_f16(o[jj * 4 + 0], o[jj * 4 + 1], o[jj * 4 + 2], o[jj * 4 + 3],
                            pa0, pa1, pa2, pa3, v0, v1);
                    mma_f16(o[jj * 4 + 4], o[jj * 4 + 5], o[jj * 4 + 6], o[jj * 4 + 7],
                            pa0, pa1, pa2, pa3, v2, v3);
                }
            }

            // ---- exp + mask for both slices ----
            float sA0 = aA0 + aB0, sA1 = aA1 + aB1;
            float sA2 = aA2 + aB2, sA3 = aA3 + aB3;
            float sB0 = bA0 + bB0, sB1 = bA1 + bB1;
            float sB2 = bA2 + bB2, sB3 = bA3 + bB3;
            float pA0, pA1, pA2, pA3, pB0, pB1, pB2, pB3;
            if (dom) {
                int kA = kt + sp * 16 + 2 * c;
                int kB = kA + 8;
                pA0 = (kA     > r0q) ? 0.f : ex2f(sA0);
                pA1 = (kA + 1 > r0q) ? 0.f : ex2f(sA1);
                pA2 = (kA     > r1q) ? 0.f : ex2f(sA2);
                pA3 = (kA + 1 > r1q) ? 0.f : ex2f(sA3);
                pB0 = (kB     > r0q) ? 0.f : ex2f(sB0);
                pB1 = (kB + 1 > r0q) ? 0.f : ex2f(sB1);
                pB2 = (kB     > r1q) ? 0.f : ex2f(sB2);
                pB3 = (kB + 1 > r1q) ? 0.f : ex2f(sB3);
            } else {
                pA0 = ex2f(sA0); pA1 = ex2f(sA1); pA2 = ex2f(sA2); pA3 = ex2f(sA3);
                pB0 = ex2f(sB0); pB1 = ex2f(sB1); pB2 = ex2f(sB2); pB3 = ex2f(sB3);
            }
            rs0 += (pA0 + pA1) + (pB0 + pB1);
            rs1 += (pA2 + pA3) + (pB2 + pB3);

            // ---- pack P into fp16 A-frag for kstep sp ----
            pa0 = pack_h2(pA0, pA1);   // A[g][k 2c,2c+1]   (slice 2sp)
            pa1 = pack_h2(pA2, pA3);   // A[g+8][k 2c,2c+1]
            pa2 = pack_h2(pB0, pB1);   // A[g][k 2c+8,2c+9] (slice 2sp+1)
            pa3 = pack_h2(pB2, pB3);   // A[g+8][k 2c+8,2c+9]
        }

        // ---- drain: PV for kstep 3 ----
        {
            uint32_t vbase_t = vBaseS + (uint32_t)(3 * 2048);
            #pragma unroll
            for (int jj = 0; jj < 8; jj += 2) {
                uint32_t v0, v1, v2, v3;
                ldsm4t(v0, v1, v2, v3, vbase_t + (uint32_t)(jj * 128));
                mma_f16(o[jj * 4 + 0], o[jj * 4 + 1], o[jj * 4 + 2], o[jj * 4 + 3],
                        pa0, pa1, pa2, pa3, v0, v1);
                mma_f16(o[jj * 4 + 4], o[jj * 4 + 5], o[jj * 4 + 6], o[jj * 4 + 7],
                        pa0, pa1, pa2, pa3, v2, v3);
            }
        }
    }

    // Reduce row sums across the quad.
    rs0 += __shfl_xor_sync(0xffffffffu, rs0, 1);
    rs0 += __shfl_xor_sync(0xffffffffu, rs0, 2);
    rs1 += __shfl_xor_sync(0xffffffffu, rs1, 1);
    rs1 += __shfl_xor_sync(0xffffffffu, rs1, 2);
    float inv0 = lw / rs0;
    float inv1 = lw / rs1;

    // Write / RMW rows r0q (c0,c1) and r0q+8 (c2,c3): cols dt*8 + 2c, +1.
    #pragma unroll
    for (int dt = 0; dt < 8; dt++) {
        float2* d0 = reinterpret_cast<float2*>(outp + dt * 8 + 2 * c);
        float2* d1 = reinterpret_cast<float2*>(outp + 8 * CDIM + dt * 8 + 2 * c);
        float2 v0 = make_float2(o[dt * 4 + 0] * inv0, o[dt * 4 + 1] * inv0);
        float2 v1 = make_float2(o[dt * 4 + 2] * inv1, o[dt * 4 + 3] * inv1);
        if (FIRST) {
            *d0 = v0; *d1 = v1;
        } else {
            float2 e0 = *d0, e1 = *d1;
            e0.x += v0.x; e0.y += v0.y; *d0 = e0;
            e1.x += v1.x; e1.y += v1.y; *d1 = e1;
        }
    }
}

__global__ __launch_bounds__(128, 3)
void xlvl_attn_f16_kernel(
    const float* __restrict__ Q,
    const float* __restrict__ K0, const float* __restrict__ V0,
    const float* __restrict__ K1, const float* __restrict__ V1,
    const float* __restrict__ K2, const float* __restrict__ V2,
    const float* __restrict__ logits,
    float* __restrict__ out,
    int T, int T1, int T2)
{
    __shared__ __align__(128) char smem[2 * KTILE_B];
    char* sK = smem;
    char* sV = smem + KTILE_B;

    const int qb  = (int)(gridDim.x - 1 - blockIdx.x);  // heavy blocks first
    const int h   = blockIdx.y;
    const int b   = blockIdx.z;
    const int tid = threadIdx.x;
    const int w   = tid >> 5;
    const int ln  = tid & 31;
    const int g   = ln >> 2;
    const int c   = ln & 3;
    const int q0  = qb * BM;
    const int r0q = q0 + w * 16 + g;

    // ldmatrix lane addresses within a tile (blocked 128B layout).
    const int lm = ln >> 3;       // matrix index 0..3
    const int lr = ln & 7;        // row within matrix
    const uint32_t kLane = (uint32_t)(lm * 128 + lr * 16);
    const uint32_t vLane = (uint32_t)((lm & 1) * 1024 + (lm >> 1) * 128 + lr * 16);

    float l0 = logits[0], l1 = logits[1], l2 = logits[2];
    float mx = fmaxf(l0, fmaxf(l1, l2));
    float e0 = __expf(l0 - mx), e1 = __expf(l1 - mx), e2 = __expf(l2 - mx);
    float winv = 1.0f / (e0 + e1 + e2);
    float w0 = e0 * winv, w1 = e1 * winv, w2 = e2 * winv;

    // Q A-fragments (fp16 RN, SCALE*log2e folded): qf[kstep][0..3].
    uint32_t qf[4][4];
    {
        const float* qp  = Q + ((size_t)(b * NHEAD + h) * T + r0q) * DH;
        const float* qp8 = qp + 8 * DH;
        #pragma unroll
        for (int t = 0; t < 4; t++) {
            int d0 = 16 * t + 2 * c;
            qf[t][0] = pack_h2(qp [d0] * SCALE_L2E, qp [d0 + 1] * SCALE_L2E);
            qf[t][1] = pack_h2(qp8[d0] * SCALE_L2E, qp8[d0 + 1] * SCALE_L2E);
            qf[t][2] = pack_h2(qp [d0 + 8] * SCALE_L2E, qp [d0 + 9] * SCALE_L2E);
            qf[t][3] = pack_h2(qp8[d0 + 8] * SCALE_L2E, qp8[d0 + 9] * SCALE_L2E);
        }
    }

    float* outp = out + ((size_t)b * T + r0q) * CDIM + h * DH;

    attend_level<true, true>(K0 + (size_t)b * T  * CDIM + h * DH,
                             V0 + (size_t)b * T  * CDIM + h * DH,
                             q0 + BM, q0, g, c, tid, r0q, qf, w0,
                             sK, sV, kLane, vLane, outp);
    attend_level<false, false>(K1 + (size_t)b * T1 * CDIM + h * DH,
                               V1 + (size_t)b * T1 * CDIM + h * DH,
                               T1, q0, g, c, tid, r0q, qf, w1,
                               sK, sV, kLane, vLane, outp);
    attend_level<false, false>(K2 + (size_t)b * T2 * CDIM + h * DH,
                               V2 + (size_t)b * T2 * CDIM + h * DH,
                               T2, q0, g, c, tid, r0q, qf, w2,
                               sK, sV, kLane, vLane, outp);
}

extern "C" void kernel_launch(void* const* d_in, const int* in_sizes, int n_in,
                              void* d_out, int out_size)
{
    const float* Q      = (const float*)d_in[0];
    const float* K0     = (const float*)d_in[1];
    const float* V0     = (const float*)d_in[2];
    const float* K1     = (const float*)d_in[3];
    const float* V1     = (const float*)d_in[4];
    const float* K2     = (const float*)d_in[5];
    const float* V2     = (const float*)d_in[6];
    const float* logits = (const float*)d_in[7];
    float* out          = (float*)d_out;

    const int B  = 2;
    const int T  = in_sizes[1] / (B * CDIM);
    const int T1 = in_sizes[3] / (B * CDIM);
    const int T2 = in_sizes[5] / (B * CDIM);

    dim3 grid(T / BM, NHEAD, B);
    xlvl_attn_f16_kernel<<<grid, 128>>>(Q, K0, V0, K1, V1, K2, V2, logits, out,
                                        T, T1, T2);
}